// round 6
// baseline (speedup 1.0000x reference)
#include <cuda_runtime.h>
#include <cuda_bf16.h>
#include <math.h>

// Problem constants
#define BB 32
#define SS 4096
#define DD 512          // OUTDIM == INDIM == 512
#define CD 1024         // concat dim
#define NSPLIT 16
#define RPS (SS / NSPLIT)   // 256 rows per split
#define WARPS 8

// Scratch (no cudaMalloc allowed)
__device__ float g_ht[BB * DD];                 // [B, D]
__device__ float g_pm[BB * NSPLIT];             // partial max
__device__ float g_pl[BB * NSPLIT];             // partial sum
__device__ float g_pacc[BB * NSPLIT * DD];      // partial weighted acc
__device__ float g_M[BB];
__device__ float g_L[BB];
__device__ float g_c[BB * DD];                  // context vectors

__device__ __forceinline__ float dot4(float4 a, float4 b) {
    return a.x * b.x + a.y * b.y + a.z * b.z + a.w * b.w;
}
__device__ __forceinline__ float warp_sum(float v) {
    #pragma unroll
    for (int o = 16; o > 0; o >>= 1) v += __shfl_xor_sync(0xFFFFFFFFu, v, o);
    return v;
}

// ---------------------------------------------------------------------------
// Length read, robust to int32 vs int64 memory_lengths.
// Real lengths are in [S/2, S] = [2048, 4096], never 0. If the buffer is
// int64 little-endian, int32 element 1 is the high word of length 0 == 0.
// If it's int32, element 1 is length 1 >= 2048 != 0. No OOB either way:
// int64 layout reads up to index 63 (256B buffer), int32 up to 31 (128B).
// Clamp to [0, SS] so a misdetection can never produce NaN/OOB downstream.
// ---------------------------------------------------------------------------
__device__ __forceinline__ int get_len(const int* __restrict__ li, int b) {
    int v = (__ldg(li + 1) == 0) ? __ldg(li + 2 * b) : __ldg(li + b);
    return min(max(v, 0), SS);
}

// ---------------------------------------------------------------------------
// Kernel 1: h_t[b, o] = dot(source[b], W_in[o]).  Warp per output row o,
// loops over all 32 batches (W_in read once from DRAM, source from cache).
// grid 64, block 256 (8 warps -> 512 output rows)
// ---------------------------------------------------------------------------
__global__ void k_ht(const float* __restrict__ src, const float* __restrict__ Win) {
    int wo = blockIdx.x * WARPS + (threadIdx.x >> 5);   // 0..511
    int lane = threadIdx.x & 31;
    const float4* wr = (const float4*)(Win + (size_t)wo * DD);
    float4 w0 = __ldg(wr + lane);
    float4 w1 = __ldg(wr + lane + 32);
    float4 w2 = __ldg(wr + lane + 64);
    float4 w3 = __ldg(wr + lane + 96);
    for (int b = 0; b < BB; b++) {
        const float4* sr = (const float4*)(src + (size_t)b * DD);
        float d = dot4(w0, __ldg(sr + lane))
                + dot4(w1, __ldg(sr + lane + 32))
                + dot4(w2, __ldg(sr + lane + 64))
                + dot4(w3, __ldg(sr + lane + 96));
        d = warp_sum(d);
        if (lane == 0) g_ht[b * DD + wo] = d;
    }
}

// ---------------------------------------------------------------------------
// Online-softmax accumulator update. s is warp-uniform (post warp_sum), so
// the s>m branch is divergence-free. Each path is ONE FMA per element and
// ONE __expf per row.
// ---------------------------------------------------------------------------
#define ACC_UPDATE(R0, R1, R2, R3)                                             \
    do {                                                                       \
        if (s > m) {                                                           \
            float sc = __expf(m - s);  /* m==-inf -> sc=0: first-row init */   \
            l = l * sc + 1.0f;                                                 \
            a0.x = a0.x * sc + R0.x; a0.y = a0.y * sc + R0.y;                  \
            a0.z = a0.z * sc + R0.z; a0.w = a0.w * sc + R0.w;                  \
            a1.x = a1.x * sc + R1.x; a1.y = a1.y * sc + R1.y;                  \
            a1.z = a1.z * sc + R1.z; a1.w = a1.w * sc + R1.w;                  \
            a2.x = a2.x * sc + R2.x; a2.y = a2.y * sc + R2.y;                  \
            a2.z = a2.z * sc + R2.z; a2.w = a2.w * sc + R2.w;                  \
            a3.x = a3.x * sc + R3.x; a3.y = a3.y * sc + R3.y;                  \
            a3.z = a3.z * sc + R3.z; a3.w = a3.w * sc + R3.w;                  \
            m = s;                                                             \
        } else {                                                               \
            float p = __expf(s - m);                                           \
            l += p;                                                            \
            a0.x += p * R0.x; a0.y += p * R0.y;                                \
            a0.z += p * R0.z; a0.w += p * R0.w;                                \
            a1.x += p * R1.x; a1.y += p * R1.y;                                \
            a1.z += p * R1.z; a1.w += p * R1.w;                                \
            a2.x += p * R2.x; a2.y += p * R2.y;                                \
            a2.z += p * R2.z; a2.w += p * R2.w;                                \
            a3.x += p * R3.x; a3.y += p * R3.y;                                \
            a3.z += p * R3.z; a3.w += p * R3.w;                                \
        }                                                                      \
    } while (0)

// ---------------------------------------------------------------------------
// Kernel 2: fused scores + online softmax + weighted accumulation.
// grid (NSPLIT, B), block 256. Warp-per-row streaming with 2-row unroll
// (MLP = 8 LDG.128 in flight per warp per body; unroll 2 keeps worst-case
// front-batched load regs at 64 so no spills under the 128-reg budget).
// Writes raw scores into the align region of d_out; k_norm finishes them.
// occ 2 (NOT 4): live set ~100 regs, occ-4 would force spills.
// ---------------------------------------------------------------------------
__global__ void __launch_bounds__(256, 2)
k_attn(const float* __restrict__ mb, const int* __restrict__ lens,
       float* __restrict__ scores_out) {
    int b = blockIdx.y;
    int split = blockIdx.x;
    int warp = threadIdx.x >> 5;
    int lane = threadIdx.x & 31;
    int len = get_len(lens, b);

    const float4* ht4 = (const float4*)(g_ht + (size_t)b * DD);
    float4 h0 = ht4[lane], h1 = ht4[lane + 32], h2 = ht4[lane + 64], h3 = ht4[lane + 96];

    float m = -INFINITY, l = 0.f;
    float4 a0 = {0,0,0,0}, a1 = {0,0,0,0}, a2 = {0,0,0,0}, a3 = {0,0,0,0};

    int base = split * RPS;
    #pragma unroll 2
    for (int i = 0; i < RPS / (2 * WARPS); i++) {
        int rA = base + warp + i * (2 * WARPS);
        int rB = rA + WARPS;
        bool vA = rA < len;
        bool vB = rB < len;
        float4 A0, A1, A2, A3, B0, B1, B2, B3;
        if (vA) {
            const float4* p = (const float4*)(mb + ((size_t)b * SS + rA) * DD);
            A0 = __ldg(p + lane); A1 = __ldg(p + lane + 32);
            A2 = __ldg(p + lane + 64); A3 = __ldg(p + lane + 96);
        }
        if (vB) {
            const float4* p = (const float4*)(mb + ((size_t)b * SS + rB) * DD);
            B0 = __ldg(p + lane); B1 = __ldg(p + lane + 32);
            B2 = __ldg(p + lane + 64); B3 = __ldg(p + lane + 96);
        }
        if (vA) {
            float s = dot4(h0, A0) + dot4(h1, A1) + dot4(h2, A2) + dot4(h3, A3);
            s = warp_sum(s);
            if (lane == 0) scores_out[b * SS + rA] = s;
            ACC_UPDATE(A0, A1, A2, A3);
        }
        if (vB) {
            float s = dot4(h0, B0) + dot4(h1, B1) + dot4(h2, B2) + dot4(h3, B3);
            s = warp_sum(s);
            if (lane == 0) scores_out[b * SS + rB] = s;
            ACC_UPDATE(B0, B1, B2, B3);
        }
    }

    // Block combine across 8 warps
    __shared__ float sm_m[WARPS], sm_l[WARPS];
    __shared__ float sm_acc[WARPS * DD];
    float4* dst = (float4*)(sm_acc + warp * DD);
    dst[lane] = a0; dst[lane + 32] = a1; dst[lane + 64] = a2; dst[lane + 96] = a3;
    if (lane == 0) { sm_m[warp] = m; sm_l[warp] = l; }
    __syncthreads();

    float M = -INFINITY;
    #pragma unroll
    for (int w = 0; w < WARPS; w++)
        if (sm_l[w] > 0.f) M = fmaxf(M, sm_m[w]);
    float sc[WARPS];
    float L = 0.f;
    #pragma unroll
    for (int w = 0; w < WARPS; w++) {
        float s = (sm_l[w] > 0.f) ? __expf(sm_m[w] - M) : 0.f;
        sc[w] = s;
        L += sm_l[w] * s;
    }
    int pidx = b * NSPLIT + split;
    #pragma unroll
    for (int rep = 0; rep < 2; rep++) {
        int d = threadIdx.x + rep * 256;
        float acc = 0.f;
        #pragma unroll
        for (int w = 0; w < WARPS; w++) acc += sm_acc[w * DD + d] * sc[w];
        g_pacc[(size_t)pidx * DD + d] = acc;
    }
    if (threadIdx.x == 0) { g_pm[pidx] = M; g_pl[pidx] = L; }
}

// ---------------------------------------------------------------------------
// Kernel 3: per-batch combine across splits -> global M, L and context c.
// grid 32, block 512
// ---------------------------------------------------------------------------
__global__ void k_comb() {
    int b = blockIdx.x;
    int tid = threadIdx.x;
    __shared__ float s_sc[NSPLIT];
    __shared__ float s_L;
    if (tid == 0) {
        float M = -INFINITY;
        #pragma unroll
        for (int s = 0; s < NSPLIT; s++)
            if (g_pl[b * NSPLIT + s] > 0.f) M = fmaxf(M, g_pm[b * NSPLIT + s]);
        float L = 0.f;
        #pragma unroll
        for (int s = 0; s < NSPLIT; s++) {
            float sc = (g_pl[b * NSPLIT + s] > 0.f) ? __expf(g_pm[b * NSPLIT + s] - M) : 0.f;
            s_sc[s] = sc;
            L += g_pl[b * NSPLIT + s] * sc;
        }
        s_L = L;
        g_M[b] = M; g_L[b] = L;
    }
    __syncthreads();
    float acc = 0.f;
    #pragma unroll
    for (int s = 0; s < NSPLIT; s++)
        acc += g_pacc[((size_t)b * NSPLIT + s) * DD + tid] * s_sc[s];
    g_c[b * DD + tid] = acc / s_L;
}

// ---------------------------------------------------------------------------
// Kernel 4: attn_h[b, o] = dot(W_out[o], concat(c[b], source[b])).
// Warp per output row o, loops over batches (W_out read once).
// grid 64, block 256
// ---------------------------------------------------------------------------
__global__ void k_out(const float* __restrict__ src, const float* __restrict__ Wout,
                      float* __restrict__ out) {
    int wo = blockIdx.x * WARPS + (threadIdx.x >> 5);   // 0..511
    int lane = threadIdx.x & 31;
    const float4* wr = (const float4*)(Wout + (size_t)wo * CD);
    float4 w[8];
    #pragma unroll
    for (int k = 0; k < 8; k++) w[k] = __ldg(wr + lane + k * 32);
    for (int b = 0; b < BB; b++) {
        const float4* cp = (const float4*)(g_c + (size_t)b * DD);
        const float4* sp = (const float4*)(src + (size_t)b * DD);
        float d = 0.f;
        #pragma unroll
        for (int k = 0; k < 4; k++) d += dot4(w[k], __ldg(cp + lane + k * 32));
        #pragma unroll
        for (int k = 0; k < 4; k++) d += dot4(w[k + 4], __ldg(sp + lane + k * 32));
        d = warp_sum(d);
        if (lane == 0) out[b * DD + wo] = d;
    }
}

// ---------------------------------------------------------------------------
// Kernel 5: normalize align region in place; masked positions -> 0.
// grid (B, S/256), block 256
// ---------------------------------------------------------------------------
__global__ void k_norm(const int* __restrict__ lens, float* __restrict__ align) {
    int b = blockIdx.x;
    int s = blockIdx.y * 256 + threadIdx.x;
    int len = get_len(lens, b);
    float* row = align + (size_t)b * SS;
    if (s < len) {
        row[s] = __expf(row[s] - g_M[b]) / g_L[b];
    } else {
        row[s] = 0.f;
    }
}

extern "C" void kernel_launch(void* const* d_in, const int* in_sizes, int n_in,
                              void* d_out, int out_size) {
    const float* src  = (const float*)d_in[0];       // [32, 1, 512]
    const float* mb   = (const float*)d_in[1];       // [32, 4096, 512]
    const int*   lens = (const int*)d_in[2];         // [32] int32 (or int64; auto-detected)
    const float* Win  = (const float*)d_in[3];       // [512, 512]
    const float* Wout = (const float*)d_in[4];       // [512, 1024]
    float* out = (float*)d_out;                      // attn_h [32,512] then align [32,4096]
    float* attn_h = out;
    float* align  = out + BB * DD;

    k_ht<<<64, 256>>>(src, Win);
    k_attn<<<dim3(NSPLIT, BB), 256>>>(mb, lens, align);
    k_comb<<<BB, 512>>>();
    k_out<<<64, 256>>>(src, Wout, attn_h);
    k_norm<<<dim3(BB, SS / 256), 256>>>(lens, align);
}

// round 7
// speedup vs baseline: 1.1004x; 1.1004x over previous
#include <cuda_runtime.h>
#include <cuda_bf16.h>
#include <math.h>

// Problem constants
#define BB 32
#define SS 4096
#define DD 512          // OUTDIM == INDIM == 512
#define CD 1024         // concat dim
#define NSPLIT 16
#define RPS (SS / NSPLIT)   // 256 rows per split
#define WARPS 8

// Scratch (no cudaMalloc allowed)
__device__ float g_ht[BB * DD];                 // [B, D]
__device__ float g_pm[BB * NSPLIT];             // partial max
__device__ float g_pl[BB * NSPLIT];             // partial sum
__device__ float g_pacc[BB * NSPLIT * DD];      // partial weighted acc
__device__ float g_M[BB];
__device__ float g_L[BB];
__device__ float g_c[BB * DD];                  // context vectors

__device__ __forceinline__ float dot4(float4 a, float4 b) {
    return a.x * b.x + a.y * b.y + a.z * b.z + a.w * b.w;
}
__device__ __forceinline__ float warp_sum(float v) {
    #pragma unroll
    for (int o = 16; o > 0; o >>= 1) v += __shfl_xor_sync(0xFFFFFFFFu, v, o);
    return v;
}

// ---------------------------------------------------------------------------
// Length read, robust to int32 vs int64 memory_lengths (see R2 post-mortem).
// Clamped to [0, SS] so a misdetection can never produce NaN/OOB downstream.
// ---------------------------------------------------------------------------
__device__ __forceinline__ int get_len(const int* __restrict__ li, int b) {
    int v = (__ldg(li + 1) == 0) ? __ldg(li + 2 * b) : __ldg(li + b);
    return min(max(v, 0), SS);
}

// ---------------------------------------------------------------------------
// Kernel 1: h_t[b, o] = dot(source[b], W_in[o]).
// RESTRUCTURED (R7): batch parallel across blockIdx.y. One dot + one
// warp_sum per warp (was: 32 serial dependent iterations). grid (64, 32)
// = 2048 blocks -> ~14 warps/SM; W_in re-read per batch hits L2 (1 MB).
// ---------------------------------------------------------------------------
__global__ void k_ht(const float* __restrict__ src, const float* __restrict__ Win) {
    int b = blockIdx.y;
    int wo = blockIdx.x * WARPS + (threadIdx.x >> 5);   // 0..511
    int lane = threadIdx.x & 31;
    const float4* wr = (const float4*)(Win + (size_t)wo * DD);
    const float4* sr = (const float4*)(src + (size_t)b * DD);
    float d = dot4(__ldg(wr + lane),      __ldg(sr + lane))
            + dot4(__ldg(wr + lane + 32), __ldg(sr + lane + 32))
            + dot4(__ldg(wr + lane + 64), __ldg(sr + lane + 64))
            + dot4(__ldg(wr + lane + 96), __ldg(sr + lane + 96));
    d = warp_sum(d);
    if (lane == 0) g_ht[b * DD + wo] = d;
}

// ---------------------------------------------------------------------------
// Online-softmax accumulator update. s is warp-uniform (post warp_sum), so
// the s>m branch is divergence-free. Each path is ONE FMA per element and
// ONE __expf per row.
// ---------------------------------------------------------------------------
#define ACC_UPDATE(R0, R1, R2, R3)                                             \
    do {                                                                       \
        if (s > m) {                                                           \
            float sc = __expf(m - s);  /* m==-inf -> sc=0: first-row init */   \
            l = l * sc + 1.0f;                                                 \
            a0.x = a0.x * sc + R0.x; a0.y = a0.y * sc + R0.y;                  \
            a0.z = a0.z * sc + R0.z; a0.w = a0.w * sc + R0.w;                  \
            a1.x = a1.x * sc + R1.x; a1.y = a1.y * sc + R1.y;                  \
            a1.z = a1.z * sc + R1.z; a1.w = a1.w * sc + R1.w;                  \
            a2.x = a2.x * sc + R2.x; a2.y = a2.y * sc + R2.y;                  \
            a2.z = a2.z * sc + R2.z; a2.w = a2.w * sc + R2.w;                  \
            a3.x = a3.x * sc + R3.x; a3.y = a3.y * sc + R3.y;                  \
            a3.z = a3.z * sc + R3.z; a3.w = a3.w * sc + R3.w;                  \
            m = s;                                                             \
        } else {                                                               \
            float p = __expf(s - m);                                           \
            l += p;                                                            \
            a0.x += p * R0.x; a0.y += p * R0.y;                                \
            a0.z += p * R0.z; a0.w += p * R0.w;                                \
            a1.x += p * R1.x; a1.y += p * R1.y;                                \
            a1.z += p * R1.z; a1.w += p * R1.w;                                \
            a2.x += p * R2.x; a2.y += p * R2.y;                                \
            a2.z += p * R2.z; a2.w += p * R2.w;                                \
            a3.x += p * R3.x; a3.y += p * R3.y;                                \
            a3.z += p * R3.z; a3.w += p * R3.w;                                \
        }                                                                      \
    } while (0)

// ---------------------------------------------------------------------------
// Kernel 2: fused scores + online softmax + weighted accumulation.
// grid (NSPLIT, B), block 256. Warp-per-row streaming with 2-row unroll
// (MLP = 8 LDG.128 in flight per warp per body). Writes raw scores into
// the align region of d_out; k_norm finishes them.  occ 2: no spills.
// ---------------------------------------------------------------------------
__global__ void __launch_bounds__(256, 2)
k_attn(const float* __restrict__ mb, const int* __restrict__ lens,
       float* __restrict__ scores_out) {
    int b = blockIdx.y;
    int split = blockIdx.x;
    int warp = threadIdx.x >> 5;
    int lane = threadIdx.x & 31;
    int len = get_len(lens, b);

    const float4* ht4 = (const float4*)(g_ht + (size_t)b * DD);
    float4 h0 = ht4[lane], h1 = ht4[lane + 32], h2 = ht4[lane + 64], h3 = ht4[lane + 96];

    float m = -INFINITY, l = 0.f;
    float4 a0 = {0,0,0,0}, a1 = {0,0,0,0}, a2 = {0,0,0,0}, a3 = {0,0,0,0};

    int base = split * RPS;
    #pragma unroll 2
    for (int i = 0; i < RPS / (2 * WARPS); i++) {
        int rA = base + warp + i * (2 * WARPS);
        int rB = rA + WARPS;
        bool vA = rA < len;
        bool vB = rB < len;
        float4 A0, A1, A2, A3, B0, B1, B2, B3;
        if (vA) {
            const float4* p = (const float4*)(mb + ((size_t)b * SS + rA) * DD);
            A0 = __ldg(p + lane); A1 = __ldg(p + lane + 32);
            A2 = __ldg(p + lane + 64); A3 = __ldg(p + lane + 96);
        }
        if (vB) {
            const float4* p = (const float4*)(mb + ((size_t)b * SS + rB) * DD);
            B0 = __ldg(p + lane); B1 = __ldg(p + lane + 32);
            B2 = __ldg(p + lane + 64); B3 = __ldg(p + lane + 96);
        }
        if (vA) {
            float s = dot4(h0, A0) + dot4(h1, A1) + dot4(h2, A2) + dot4(h3, A3);
            s = warp_sum(s);
            if (lane == 0) scores_out[b * SS + rA] = s;
            ACC_UPDATE(A0, A1, A2, A3);
        }
        if (vB) {
            float s = dot4(h0, B0) + dot4(h1, B1) + dot4(h2, B2) + dot4(h3, B3);
            s = warp_sum(s);
            if (lane == 0) scores_out[b * SS + rB] = s;
            ACC_UPDATE(B0, B1, B2, B3);
        }
    }

    // Block combine across 8 warps
    __shared__ float sm_m[WARPS], sm_l[WARPS];
    __shared__ float sm_acc[WARPS * DD];
    float4* dst = (float4*)(sm_acc + warp * DD);
    dst[lane] = a0; dst[lane + 32] = a1; dst[lane + 64] = a2; dst[lane + 96] = a3;
    if (lane == 0) { sm_m[warp] = m; sm_l[warp] = l; }
    __syncthreads();

    float M = -INFINITY;
    #pragma unroll
    for (int w = 0; w < WARPS; w++)
        if (sm_l[w] > 0.f) M = fmaxf(M, sm_m[w]);
    float sc[WARPS];
    float L = 0.f;
    #pragma unroll
    for (int w = 0; w < WARPS; w++) {
        float s = (sm_l[w] > 0.f) ? __expf(sm_m[w] - M) : 0.f;
        sc[w] = s;
        L += sm_l[w] * s;
    }
    int pidx = b * NSPLIT + split;
    #pragma unroll
    for (int rep = 0; rep < 2; rep++) {
        int d = threadIdx.x + rep * 256;
        float acc = 0.f;
        #pragma unroll
        for (int w = 0; w < WARPS; w++) acc += sm_acc[w * DD + d] * sc[w];
        g_pacc[(size_t)pidx * DD + d] = acc;
    }
    if (threadIdx.x == 0) { g_pm[pidx] = M; g_pl[pidx] = L; }
}

// ---------------------------------------------------------------------------
// Kernel 3: per-batch combine across splits -> global M, L and context c.
// grid 32, block 512
// ---------------------------------------------------------------------------
__global__ void k_comb() {
    int b = blockIdx.x;
    int tid = threadIdx.x;
    __shared__ float s_sc[NSPLIT];
    __shared__ float s_L;
    if (tid == 0) {
        float M = -INFINITY;
        #pragma unroll
        for (int s = 0; s < NSPLIT; s++)
            if (g_pl[b * NSPLIT + s] > 0.f) M = fmaxf(M, g_pm[b * NSPLIT + s]);
        float L = 0.f;
        #pragma unroll
        for (int s = 0; s < NSPLIT; s++) {
            float sc = (g_pl[b * NSPLIT + s] > 0.f) ? __expf(g_pm[b * NSPLIT + s] - M) : 0.f;
            s_sc[s] = sc;
            L += g_pl[b * NSPLIT + s] * sc;
        }
        s_L = L;
        g_M[b] = M; g_L[b] = L;
    }
    __syncthreads();
    float acc = 0.f;
    #pragma unroll
    for (int s = 0; s < NSPLIT; s++)
        acc += g_pacc[((size_t)b * NSPLIT + s) * DD + tid] * s_sc[s];
    g_c[b * DD + tid] = acc / s_L;
}

// ---------------------------------------------------------------------------
// Kernel 4: attn_h[b, o] = dot(W_out[o], concat(c[b], source[b])).
// RESTRUCTURED (R7): batch parallel across blockIdx.y, one dot + one
// warp_sum per warp. grid (64, 32); W_out (2 MB) re-read per batch -> L2.
// ---------------------------------------------------------------------------
__global__ void k_out(const float* __restrict__ src, const float* __restrict__ Wout,
                      float* __restrict__ out) {
    int b = blockIdx.y;
    int wo = blockIdx.x * WARPS + (threadIdx.x >> 5);   // 0..511
    int lane = threadIdx.x & 31;
    const float4* wr = (const float4*)(Wout + (size_t)wo * CD);
    const float4* cp = (const float4*)(g_c + (size_t)b * DD);
    const float4* sp = (const float4*)(src + (size_t)b * DD);
    float d = 0.f;
    #pragma unroll
    for (int k = 0; k < 4; k++) d += dot4(__ldg(wr + lane + k * 32), __ldg(cp + lane + k * 32));
    #pragma unroll
    for (int k = 0; k < 4; k++) d += dot4(__ldg(wr + lane + (k + 4) * 32), __ldg(sp + lane + k * 32));
    d = warp_sum(d);
    if (lane == 0) out[b * DD + wo] = d;
}

// ---------------------------------------------------------------------------
// Kernel 5: normalize align region in place; masked positions -> 0.
// grid (B, S/256), block 256
// ---------------------------------------------------------------------------
__global__ void k_norm(const int* __restrict__ lens, float* __restrict__ align) {
    int b = blockIdx.x;
    int s = blockIdx.y * 256 + threadIdx.x;
    int len = get_len(lens, b);
    float* row = align + (size_t)b * SS;
    if (s < len) {
        row[s] = __expf(row[s] - g_M[b]) / g_L[b];
    } else {
        row[s] = 0.f;
    }
}

extern "C" void kernel_launch(void* const* d_in, const int* in_sizes, int n_in,
                              void* d_out, int out_size) {
    const float* src  = (const float*)d_in[0];       // [32, 1, 512]
    const float* mb   = (const float*)d_in[1];       // [32, 4096, 512]
    const int*   lens = (const int*)d_in[2];         // [32] int32 (or int64; auto-detected)
    const float* Win  = (const float*)d_in[3];       // [512, 512]
    const float* Wout = (const float*)d_in[4];       // [512, 1024]
    float* out = (float*)d_out;                      // attn_h [32,512] then align [32,4096]
    float* attn_h = out;
    float* align  = out + BB * DD;

    k_ht<<<dim3(64, BB), 256>>>(src, Win);
    k_attn<<<dim3(NSPLIT, BB), 256>>>(mb, lens, align);
    k_comb<<<BB, 512>>>();
    k_out<<<dim3(64, BB), 256>>>(src, Wout, attn_h);
    k_norm<<<dim3(BB, SS / 256), 256>>>(lens, align);
}

// round 9
// speedup vs baseline: 1.4951x; 1.3587x over previous
#include <cuda_runtime.h>
#include <cuda_bf16.h>
#include <math.h>

// Problem constants
#define BB 32
#define SS 4096
#define DD 512          // OUTDIM == INDIM == 512
#define CD 1024         // concat dim
#define NSPLIT 16
#define RPS (SS / NSPLIT)   // 256 rows per split
#define WARPS 8

// Scratch (no cudaMalloc allowed)
__device__ float g_ht[BB * DD];                 // [B, D]
__device__ float g_pm[BB * NSPLIT];             // partial max
__device__ float g_pl[BB * NSPLIT];             // partial sum
__device__ float g_pacc[BB * NSPLIT * DD];      // partial weighted acc

__device__ __forceinline__ float dot4(float4 a, float4 b) {
    return a.x * b.x + a.y * b.y + a.z * b.z + a.w * b.w;
}
__device__ __forceinline__ float warp_sum(float v) {
    #pragma unroll
    for (int o = 16; o > 0; o >>= 1) v += __shfl_xor_sync(0xFFFFFFFFu, v, o);
    return v;
}
__device__ __forceinline__ float warp_max(float v) {
    #pragma unroll
    for (int o = 16; o > 0; o >>= 1) v = fmaxf(v, __shfl_xor_sync(0xFFFFFFFFu, v, o));
    return v;
}

// ---------------------------------------------------------------------------
// Length read, robust to int32 vs int64 memory_lengths (see R2 post-mortem).
// Clamped to [0, SS] so a misdetection can never produce NaN/OOB downstream.
// ---------------------------------------------------------------------------
__device__ __forceinline__ int get_len(const int* __restrict__ li, int b) {
    int v = (__ldg(li + 1) == 0) ? __ldg(li + 2 * b) : __ldg(li + b);
    return min(max(v, 0), SS);
}

// ---------------------------------------------------------------------------
// Kernel 1: h_t[b, o] = dot(source[b], W_in[o]).
// R8: 4 batches per warp (grid 64 x 8). W_in regs loaded once per warp,
// 4 independent dot + shfl chains -> 4x ILP, W_in L2 traffic 32MB -> 8MB.
// ---------------------------------------------------------------------------
__global__ void k_ht(const float* __restrict__ src, const float* __restrict__ Win) {
    int b0 = blockIdx.y * 4;
    int wo = blockIdx.x * WARPS + (threadIdx.x >> 5);   // 0..511
    int lane = threadIdx.x & 31;
    const float4* wr = (const float4*)(Win + (size_t)wo * DD);
    float4 w0 = __ldg(wr + lane);
    float4 w1 = __ldg(wr + lane + 32);
    float4 w2 = __ldg(wr + lane + 64);
    float4 w3 = __ldg(wr + lane + 96);
    float d[4];
    #pragma unroll
    for (int j = 0; j < 4; j++) {
        const float4* sr = (const float4*)(src + (size_t)(b0 + j) * DD);
        d[j] = dot4(w0, __ldg(sr + lane))
             + dot4(w1, __ldg(sr + lane + 32))
             + dot4(w2, __ldg(sr + lane + 64))
             + dot4(w3, __ldg(sr + lane + 96));
    }
    #pragma unroll
    for (int j = 0; j < 4; j++) d[j] = warp_sum(d[j]);
    if (lane == 0) {
        #pragma unroll
        for (int j = 0; j < 4; j++) g_ht[(b0 + j) * DD + wo] = d[j];
    }
}

// ---------------------------------------------------------------------------
// Online-softmax accumulator update. s is warp-uniform (post warp_sum), so
// the s>m branch is divergence-free. One FMA/elem + one __expf per row.
// ---------------------------------------------------------------------------
#define ACC_UPDATE(R0, R1, R2, R3)                                             \
    do {                                                                       \
        if (s > m) {                                                           \
            float sc = __expf(m - s);  /* m==-inf -> sc=0: first-row init */   \
            l = l * sc + 1.0f;                                                 \
            a0.x = a0.x * sc + R0.x; a0.y = a0.y * sc + R0.y;                  \
            a0.z = a0.z * sc + R0.z; a0.w = a0.w * sc + R0.w;                  \
            a1.x = a1.x * sc + R1.x; a1.y = a1.y * sc + R1.y;                  \
            a1.z = a1.z * sc + R1.z; a1.w = a1.w * sc + R1.w;                  \
            a2.x = a2.x * sc + R2.x; a2.y = a2.y * sc + R2.y;                  \
            a2.z = a2.z * sc + R2.z; a2.w = a2.w * sc + R2.w;                  \
            a3.x = a3.x * sc + R3.x; a3.y = a3.y * sc + R3.y;                  \
            a3.z = a3.z * sc + R3.z; a3.w = a3.w * sc + R3.w;                  \
            m = s;                                                             \
        } else {                                                               \
            float p = __expf(s - m);                                           \
            l += p;                                                            \
            a0.x += p * R0.x; a0.y += p * R0.y;                                \
            a0.z += p * R0.z; a0.w += p * R0.w;                                \
            a1.x += p * R1.x; a1.y += p * R1.y;                                \
            a1.z += p * R1.z; a1.w += p * R1.w;                                \
            a2.x += p * R2.x; a2.y += p * R2.y;                                \
            a2.z += p * R2.z; a2.w += p * R2.w;                                \
            a3.x += p * R3.x; a3.y += p * R3.y;                                \
            a3.z += p * R3.z; a3.w += p * R3.w;                                \
        }                                                                      \
    } while (0)

// ---------------------------------------------------------------------------
// Kernel 2: fused scores + online softmax + weighted accumulation.
// grid (NSPLIT, B), block 256. Warp-per-row streaming, 2-row unroll.
// UNCHANGED from R7 for attribution.
// ---------------------------------------------------------------------------
__global__ void __launch_bounds__(256, 2)
k_attn(const float* __restrict__ mb, const int* __restrict__ lens,
       float* __restrict__ scores_out) {
    int b = blockIdx.y;
    int split = blockIdx.x;
    int warp = threadIdx.x >> 5;
    int lane = threadIdx.x & 31;
    int len = get_len(lens, b);

    const float4* ht4 = (const float4*)(g_ht + (size_t)b * DD);
    float4 h0 = ht4[lane], h1 = ht4[lane + 32], h2 = ht4[lane + 64], h3 = ht4[lane + 96];

    float m = -INFINITY, l = 0.f;
    float4 a0 = {0,0,0,0}, a1 = {0,0,0,0}, a2 = {0,0,0,0}, a3 = {0,0,0,0};

    int base = split * RPS;
    #pragma unroll 2
    for (int i = 0; i < RPS / (2 * WARPS); i++) {
        int rA = base + warp + i * (2 * WARPS);
        int rB = rA + WARPS;
        bool vA = rA < len;
        bool vB = rB < len;
        float4 A0, A1, A2, A3, B0, B1, B2, B3;
        if (vA) {
            const float4* p = (const float4*)(mb + ((size_t)b * SS + rA) * DD);
            A0 = __ldg(p + lane); A1 = __ldg(p + lane + 32);
            A2 = __ldg(p + lane + 64); A3 = __ldg(p + lane + 96);
        }
        if (vB) {
            const float4* p = (const float4*)(mb + ((size_t)b * SS + rB) * DD);
            B0 = __ldg(p + lane); B1 = __ldg(p + lane + 32);
            B2 = __ldg(p + lane + 64); B3 = __ldg(p + lane + 96);
        }
        if (vA) {
            float s = dot4(h0, A0) + dot4(h1, A1) + dot4(h2, A2) + dot4(h3, A3);
            s = warp_sum(s);
            if (lane == 0) scores_out[b * SS + rA] = s;
            ACC_UPDATE(A0, A1, A2, A3);
        }
        if (vB) {
            float s = dot4(h0, B0) + dot4(h1, B1) + dot4(h2, B2) + dot4(h3, B3);
            s = warp_sum(s);
            if (lane == 0) scores_out[b * SS + rB] = s;
            ACC_UPDATE(B0, B1, B2, B3);
        }
    }

    // Block combine across 8 warps
    __shared__ float sm_m[WARPS], sm_l[WARPS];
    __shared__ float sm_acc[WARPS * DD];
    float4* dst = (float4*)(sm_acc + warp * DD);
    dst[lane] = a0; dst[lane + 32] = a1; dst[lane + 64] = a2; dst[lane + 96] = a3;
    if (lane == 0) { sm_m[warp] = m; sm_l[warp] = l; }
    __syncthreads();

    float M = -INFINITY;
    #pragma unroll
    for (int w = 0; w < WARPS; w++)
        if (sm_l[w] > 0.f) M = fmaxf(M, sm_m[w]);
    float sc[WARPS];
    float L = 0.f;
    #pragma unroll
    for (int w = 0; w < WARPS; w++) {
        float s = (sm_l[w] > 0.f) ? __expf(sm_m[w] - M) : 0.f;
        sc[w] = s;
        L += sm_l[w] * s;
    }
    int pidx = b * NSPLIT + split;
    #pragma unroll
    for (int rep = 0; rep < 2; rep++) {
        int d = threadIdx.x + rep * 256;
        float acc = 0.f;
        #pragma unroll
        for (int w = 0; w < WARPS; w++) acc += sm_acc[w * DD + d] * sc[w];
        g_pacc[(size_t)pidx * DD + d] = acc;
    }
    if (threadIdx.x == 0) { g_pm[pidx] = M; g_pl[pidx] = L; }
}

// ---------------------------------------------------------------------------
// Kernel 3 (R8 fusion of k_comb + k_out + k_norm): grid (48, 16), block 512.
// blockIdx.y = batch PAIR (b0 = 2*pair). Roles by blockIdx.x:
//  [0,32):  GEMM role. Per block: split-combine sc/L/M from g_pm/g_pl
//           (warps 0-1), build c[2][512] in smem, then 16 warps each compute
//           out[b0][wo] and out[b0+1][wo] with W_out row in regs (2 indep
//           chains -> 2x ILP, W_out traffic halved to 32MB).
//  [32,48): norm role. Recompute M,L in-block, normalize 512 align
//           positions of one batch (8 blocks per batch).
// ---------------------------------------------------------------------------
__global__ void __launch_bounds__(512)
k_post(const float* __restrict__ src, const float* __restrict__ Wout,
       const int* __restrict__ lens,
       float* __restrict__ attn_h, float* __restrict__ align) {
    __shared__ float s_c[2][DD];          // context vectors for the pair
    __shared__ float s_sc[2][NSPLIT];     // split scale factors
    __shared__ float s_L[2], s_M[2];

    int bx = blockIdx.x;
    int b0 = blockIdx.y * 2;
    int tid = threadIdx.x;
    int warp = tid >> 5;
    int lane = tid & 31;

    if (bx < 32) {
        // ---- stage 1: split-combine (warps 0,1: one batch each) ----
        if (warp < 2) {
            int b = b0 + warp;
            float pm = (lane < NSPLIT) ? g_pm[b * NSPLIT + lane] : -INFINITY;
            float pl = (lane < NSPLIT) ? g_pl[b * NSPLIT + lane] : 0.f;
            float M = warp_max((pl > 0.f) ? pm : -INFINITY);
            float e = (pl > 0.f) ? __expf(pm - M) : 0.f;
            float L = warp_sum(e * pl);
            if (lane < NSPLIT) s_sc[warp][lane] = e;
            if (lane == 0) { s_L[warp] = L; s_M[warp] = M; }
        }
        __syncthreads();
        // ---- stage 2: c[j][d] = sum_s pacc * sc / L  (coalesced over tid) ----
        #pragma unroll
        for (int j = 0; j < 2; j++) {
            float acc = 0.f;
            #pragma unroll
            for (int s = 0; s < NSPLIT; s++)
                acc += g_pacc[(size_t)((b0 + j) * NSPLIT + s) * DD + tid] * s_sc[j][s];
            s_c[j][tid] = acc / s_L[j];
        }
        __syncthreads();
        // ---- stage 3: warp-per-row dot, 2 batches per warp ----
        int wo = bx * 16 + warp;            // 0..511
        const float4* wr = (const float4*)(Wout + (size_t)wo * CD);
        float4 w[8];
        #pragma unroll
        for (int k = 0; k < 8; k++) w[k] = __ldg(wr + lane + k * 32);
        const float4* c0 = (const float4*)s_c[0];
        const float4* c1 = (const float4*)s_c[1];
        const float4* s0 = (const float4*)(src + (size_t)b0 * DD);
        const float4* s1 = (const float4*)(src + (size_t)(b0 + 1) * DD);
        float d0 = 0.f, d1 = 0.f;
        #pragma unroll
        for (int k = 0; k < 4; k++) {
            d0 += dot4(w[k], c0[lane + k * 32]);
            d1 += dot4(w[k], c1[lane + k * 32]);
        }
        #pragma unroll
        for (int k = 0; k < 4; k++) {
            float4 wv = w[k + 4];
            d0 += dot4(wv, __ldg(s0 + lane + k * 32));
            d1 += dot4(wv, __ldg(s1 + lane + k * 32));
        }
        d0 = warp_sum(d0);
        d1 = warp_sum(d1);
        if (lane == 0) {
            attn_h[b0 * DD + wo] = d0;
            attn_h[(b0 + 1) * DD + wo] = d1;
        }
    } else {
        // ---- norm role ----
        int nx = bx - 32;                   // 0..15
        int j = nx >> 3;                    // which batch of the pair
        int b = b0 + j;
        if (warp == 0) {
            float pm = (lane < NSPLIT) ? g_pm[b * NSPLIT + lane] : -INFINITY;
            float pl = (lane < NSPLIT) ? g_pl[b * NSPLIT + lane] : 0.f;
            float M = warp_max((pl > 0.f) ? pm : -INFINITY);
            float e = (pl > 0.f) ? __expf(pm - M) : 0.f;
            float L = warp_sum(e * pl);
            if (lane == 0) { s_L[0] = L; s_M[0] = M; }
        }
        __syncthreads();
        int len = get_len(lens, b);
        int p = (nx & 7) * 512 + tid;
        float* row = align + (size_t)b * SS;
        row[p] = (p < len) ? __expf(row[p] - s_M[0]) / s_L[0] : 0.f;
    }
}

extern "C" void kernel_launch(void* const* d_in, const int* in_sizes, int n_in,
                              void* d_out, int out_size) {
    const float* src  = (const float*)d_in[0];       // [32, 1, 512]
    const float* mb   = (const float*)d_in[1];       // [32, 4096, 512]
    const int*   lens = (const int*)d_in[2];         // [32] int32/int64 auto
    const float* Win  = (const float*)d_in[3];       // [512, 512]
    const float* Wout = (const float*)d_in[4];       // [512, 1024]
    float* out = (float*)d_out;                      // attn_h [32,512] ++ align [32,4096]
    float* attn_h = out;
    float* align  = out + BB * DD;

    k_ht<<<dim3(64, 8), 256>>>(src, Win);
    k_attn<<<dim3(NSPLIT, BB), 256>>>(mb, lens, align);
    k_post<<<dim3(48, BB / 2), 512>>>(src, Wout, lens, attn_h, align);
}

// round 10
// speedup vs baseline: 1.6193x; 1.0831x over previous
#include <cuda_runtime.h>
#include <cuda_bf16.h>
#include <math.h>

// Problem constants
#define BB 32
#define SS 4096
#define DD 512          // OUTDIM == INDIM == 512
#define CD 1024         // concat dim
#define NSPLIT 16
#define RPS (SS / NSPLIT)   // 256 rows per split (interleaved stride-16)
#define WARPS 8

// Scratch (no cudaMalloc allowed)
__device__ float g_ht[BB * DD];                 // [B, D]
__device__ float g_pm[BB * NSPLIT];             // partial max
__device__ float g_pl[BB * NSPLIT];             // partial sum
__device__ float g_pacc[BB * NSPLIT * DD];      // partial weighted acc

__device__ __forceinline__ float dot4(float4 a, float4 b) {
    return a.x * b.x + a.y * b.y + a.z * b.z + a.w * b.w;
}
__device__ __forceinline__ float warp_sum(float v) {
    #pragma unroll
    for (int o = 16; o > 0; o >>= 1) v += __shfl_xor_sync(0xFFFFFFFFu, v, o);
    return v;
}
__device__ __forceinline__ float warp_max(float v) {
    #pragma unroll
    for (int o = 16; o > 0; o >>= 1) v = fmaxf(v, __shfl_xor_sync(0xFFFFFFFFu, v, o));
    return v;
}

// ---------------------------------------------------------------------------
// Length read, robust to int32 vs int64 memory_lengths (see R2 post-mortem).
// Clamped to [0, SS] so a misdetection can never produce NaN/OOB downstream.
// ---------------------------------------------------------------------------
__device__ __forceinline__ int get_len(const int* __restrict__ li, int b) {
    int v = (__ldg(li + 1) == 0) ? __ldg(li + 2 * b) : __ldg(li + b);
    return min(max(v, 0), SS);
}

// ---------------------------------------------------------------------------
// Kernel 1: h_t[b, o] = dot(source[b], W_in[o]).
// 4 batches per warp (grid 64 x 8). W_in regs loaded once per warp,
// 4 independent dot + shfl chains -> 4x ILP. Unchanged from R9.
// ---------------------------------------------------------------------------
__global__ void k_ht(const float* __restrict__ src, const float* __restrict__ Win) {
    int b0 = blockIdx.y * 4;
    int wo = blockIdx.x * WARPS + (threadIdx.x >> 5);   // 0..511
    int lane = threadIdx.x & 31;
    const float4* wr = (const float4*)(Win + (size_t)wo * DD);
    float4 w0 = __ldg(wr + lane);
    float4 w1 = __ldg(wr + lane + 32);
    float4 w2 = __ldg(wr + lane + 64);
    float4 w3 = __ldg(wr + lane + 96);
    float d[4];
    #pragma unroll
    for (int j = 0; j < 4; j++) {
        const float4* sr = (const float4*)(src + (size_t)(b0 + j) * DD);
        d[j] = dot4(w0, __ldg(sr + lane))
             + dot4(w1, __ldg(sr + lane + 32))
             + dot4(w2, __ldg(sr + lane + 64))
             + dot4(w3, __ldg(sr + lane + 96));
    }
    #pragma unroll
    for (int j = 0; j < 4; j++) d[j] = warp_sum(d[j]);
    if (lane == 0) {
        #pragma unroll
        for (int j = 0; j < 4; j++) g_ht[(b0 + j) * DD + wo] = d[j];
    }
}

// ---------------------------------------------------------------------------
// Online-softmax accumulator update. s is warp-uniform (post warp_sum), so
// the s>m branch is divergence-free. One FMA/elem + one __expf per row.
// ---------------------------------------------------------------------------
#define ACC_UPDATE(R0, R1, R2, R3)                                             \
    do {                                                                       \
        if (s > m) {                                                           \
            float sc = __expf(m - s);  /* m==-inf -> sc=0: first-row init */   \
            l = l * sc + 1.0f;                                                 \
            a0.x = a0.x * sc + R0.x; a0.y = a0.y * sc + R0.y;                  \
            a0.z = a0.z * sc + R0.z; a0.w = a0.w * sc + R0.w;                  \
            a1.x = a1.x * sc + R1.x; a1.y = a1.y * sc + R1.y;                  \
            a1.z = a1.z * sc + R1.z; a1.w = a1.w * sc + R1.w;                  \
            a2.x = a2.x * sc + R2.x; a2.y = a2.y * sc + R2.y;                  \
            a2.z = a2.z * sc + R2.z; a2.w = a2.w * sc + R2.w;                  \
            a3.x = a3.x * sc + R3.x; a3.y = a3.y * sc + R3.y;                  \
            a3.z = a3.z * sc + R3.z; a3.w = a3.w * sc + R3.w;                  \
            m = s;                                                             \
        } else {                                                               \
            float p = __expf(s - m);                                           \
            l += p;                                                            \
            a0.x += p * R0.x; a0.y += p * R0.y;                                \
            a0.z += p * R0.z; a0.w += p * R0.w;                                \
            a1.x += p * R1.x; a1.y += p * R1.y;                                \
            a1.z += p * R1.z; a1.w += p * R1.w;                                \
            a2.x += p * R2.x; a2.y += p * R2.y;                                \
            a2.z += p * R2.z; a2.w += p * R2.w;                                \
            a3.x += p * R3.x; a3.y += p * R3.y;                                \
            a3.z += p * R3.z; a3.w += p * R3.w;                                \
        }                                                                      \
    } while (0)

// ---------------------------------------------------------------------------
// Kernel 2: fused scores + online softmax + weighted accumulation.
// grid (NSPLIT, B), block 256.
// R10: INTERLEAVED split mapping — split sp covers rows {sp + 16k}. The
// masked suffix [len, 4096) now distributes evenly over all 16 splits, so
// every block of a batch does ~len/16 rows (was 0..256: severe imbalance).
// Warp-per-row, 2-row unroll (8 LDG.128 in flight per warp per body).
// ---------------------------------------------------------------------------
__global__ void __launch_bounds__(256, 2)
k_attn(const float* __restrict__ mb, const int* __restrict__ lens,
       float* __restrict__ scores_out) {
    int b = blockIdx.y;
    int split = blockIdx.x;
    int warp = threadIdx.x >> 5;
    int lane = threadIdx.x & 31;
    int len = get_len(lens, b);

    const float4* ht4 = (const float4*)(g_ht + (size_t)b * DD);
    float4 h0 = ht4[lane], h1 = ht4[lane + 32], h2 = ht4[lane + 64], h3 = ht4[lane + 96];

    float m = -INFINITY, l = 0.f;
    float4 a0 = {0,0,0,0}, a1 = {0,0,0,0}, a2 = {0,0,0,0}, a3 = {0,0,0,0};

    // rows: rA = split + 16*(warp + 16*i), rB = rA + 128  (i in [0,16))
    // covers k = warp+16i and k = warp+8+16i over i -> all k in [0,256)
    #pragma unroll 2
    for (int i = 0; i < RPS / (2 * WARPS); i++) {
        int rA = split + NSPLIT * (warp + 2 * WARPS * i);
        int rB = rA + NSPLIT * WARPS;
        bool vA = rA < len;
        bool vB = rB < len;
        float4 A0, A1, A2, A3, B0, B1, B2, B3;
        if (vA) {
            const float4* p = (const float4*)(mb + ((size_t)b * SS + rA) * DD);
            A0 = __ldg(p + lane); A1 = __ldg(p + lane + 32);
            A2 = __ldg(p + lane + 64); A3 = __ldg(p + lane + 96);
        }
        if (vB) {
            const float4* p = (const float4*)(mb + ((size_t)b * SS + rB) * DD);
            B0 = __ldg(p + lane); B1 = __ldg(p + lane + 32);
            B2 = __ldg(p + lane + 64); B3 = __ldg(p + lane + 96);
        }
        if (vA) {
            float s = dot4(h0, A0) + dot4(h1, A1) + dot4(h2, A2) + dot4(h3, A3);
            s = warp_sum(s);
            if (lane == 0) scores_out[b * SS + rA] = s;
            ACC_UPDATE(A0, A1, A2, A3);
        }
        if (vB) {
            float s = dot4(h0, B0) + dot4(h1, B1) + dot4(h2, B2) + dot4(h3, B3);
            s = warp_sum(s);
            if (lane == 0) scores_out[b * SS + rB] = s;
            ACC_UPDATE(B0, B1, B2, B3);
        }
    }

    // Block combine across 8 warps
    __shared__ float sm_m[WARPS], sm_l[WARPS];
    __shared__ float sm_acc[WARPS * DD];
    float4* dst = (float4*)(sm_acc + warp * DD);
    dst[lane] = a0; dst[lane + 32] = a1; dst[lane + 64] = a2; dst[lane + 96] = a3;
    if (lane == 0) { sm_m[warp] = m; sm_l[warp] = l; }
    __syncthreads();

    float M = -INFINITY;
    #pragma unroll
    for (int w = 0; w < WARPS; w++)
        if (sm_l[w] > 0.f) M = fmaxf(M, sm_m[w]);
    float sc[WARPS];
    float L = 0.f;
    #pragma unroll
    for (int w = 0; w < WARPS; w++) {
        float s = (sm_l[w] > 0.f) ? __expf(sm_m[w] - M) : 0.f;
        sc[w] = s;
        L += sm_l[w] * s;
    }
    int pidx = b * NSPLIT + split;
    #pragma unroll
    for (int rep = 0; rep < 2; rep++) {
        int d = threadIdx.x + rep * 256;
        float acc = 0.f;
        #pragma unroll
        for (int w = 0; w < WARPS; w++) acc += sm_acc[w * DD + d] * sc[w];
        g_pacc[(size_t)pidx * DD + d] = acc;
    }
    if (threadIdx.x == 0) { g_pm[pidx] = M; g_pl[pidx] = L; }
}

// ---------------------------------------------------------------------------
// Kernel 3 (fused comb+out+norm): grid (64, 8), block 512.
// blockIdx.y = batch QUAD (b0 = 4*quad). Roles by blockIdx.x:
//  [0,32):  GEMM role. Warps 0-3 split-combine one batch each; build
//           c[4][512] in smem; then 16 warps each compute out[b0..b0+3][wo]
//           with the W_out row in regs (4 indep chains -> 4x ILP, W_out
//           traffic 16MB).
//  [32,64): norm role. nx = bx-32: batch b0 + (nx>>3), positions
//           (nx&7)*512 + tid.
// ---------------------------------------------------------------------------
__global__ void __launch_bounds__(512)
k_post(const float* __restrict__ src, const float* __restrict__ Wout,
       const int* __restrict__ lens,
       float* __restrict__ attn_h, float* __restrict__ align) {
    __shared__ float s_c[4][DD];          // context vectors for the quad
    __shared__ float s_sc[4][NSPLIT];     // split scale factors
    __shared__ float s_L[4], s_M[4];

    int bx = blockIdx.x;
    int b0 = blockIdx.y * 4;
    int tid = threadIdx.x;
    int warp = tid >> 5;
    int lane = tid & 31;

    if (bx < 32) {
        // ---- stage 1: split-combine (warps 0-3: one batch each) ----
        if (warp < 4) {
            int b = b0 + warp;
            float pm = (lane < NSPLIT) ? g_pm[b * NSPLIT + lane] : -INFINITY;
            float pl = (lane < NSPLIT) ? g_pl[b * NSPLIT + lane] : 0.f;
            float M = warp_max((pl > 0.f) ? pm : -INFINITY);
            float e = (pl > 0.f) ? __expf(pm - M) : 0.f;
            float L = warp_sum(e * pl);
            if (lane < NSPLIT) s_sc[warp][lane] = e;
            if (lane == 0) { s_L[warp] = L; s_M[warp] = M; }
        }
        __syncthreads();
        // ---- stage 2: c[j][d] = sum_s pacc * sc / L  (coalesced over tid) ----
        #pragma unroll
        for (int j = 0; j < 4; j++) {
            float acc = 0.f;
            #pragma unroll
            for (int s = 0; s < NSPLIT; s++)
                acc += g_pacc[(size_t)((b0 + j) * NSPLIT + s) * DD + tid] * s_sc[j][s];
            s_c[j][tid] = acc / s_L[j];
        }
        __syncthreads();
        // ---- stage 3: warp-per-row dot, 4 batches per warp ----
        int wo = bx * 16 + warp;            // 0..511
        const float4* wr = (const float4*)(Wout + (size_t)wo * CD);
        float4 w[8];
        #pragma unroll
        for (int k = 0; k < 8; k++) w[k] = __ldg(wr + lane + k * 32);
        float d[4] = {0.f, 0.f, 0.f, 0.f};
        #pragma unroll
        for (int j = 0; j < 4; j++) {
            const float4* cj = (const float4*)s_c[j];
            #pragma unroll
            for (int k = 0; k < 4; k++) d[j] += dot4(w[k], cj[lane + k * 32]);
        }
        #pragma unroll
        for (int j = 0; j < 4; j++) {
            const float4* sj = (const float4*)(src + (size_t)(b0 + j) * DD);
            #pragma unroll
            for (int k = 0; k < 4; k++) d[j] += dot4(w[k + 4], __ldg(sj + lane + k * 32));
        }
        #pragma unroll
        for (int j = 0; j < 4; j++) d[j] = warp_sum(d[j]);
        if (lane == 0) {
            #pragma unroll
            for (int j = 0; j < 4; j++) attn_h[(b0 + j) * DD + wo] = d[j];
        }
    } else {
        // ---- norm role ----
        int nx = bx - 32;                   // 0..31
        int j = nx >> 3;                    // which batch of the quad
        int b = b0 + j;
        if (warp == 0) {
            float pm = (lane < NSPLIT) ? g_pm[b * NSPLIT + lane] : -INFINITY;
            float pl = (lane < NSPLIT) ? g_pl[b * NSPLIT + lane] : 0.f;
            float M = warp_max((pl > 0.f) ? pm : -INFINITY);
            float e = (pl > 0.f) ? __expf(pm - M) : 0.f;
            float L = warp_sum(e * pl);
            if (lane == 0) { s_L[0] = L; s_M[0] = M; }
        }
        __syncthreads();
        int len = get_len(lens, b);
        int p = (nx & 7) * 512 + tid;
        float* row = align + (size_t)b * SS;
        row[p] = (p < len) ? __expf(row[p] - s_M[0]) / s_L[0] : 0.f;
    }
}

extern "C" void kernel_launch(void* const* d_in, const int* in_sizes, int n_in,
                              void* d_out, int out_size) {
    const float* src  = (const float*)d_in[0];       // [32, 1, 512]
    const float* mb   = (const float*)d_in[1];       // [32, 4096, 512]
    const int*   lens = (const int*)d_in[2];         // [32] int32/int64 auto
    const float* Win  = (const float*)d_in[3];       // [512, 512]
    const float* Wout = (const float*)d_in[4];       // [512, 1024]
    float* out = (float*)d_out;                      // attn_h [32,512] ++ align [32,4096]
    float* attn_h = out;
    float* align  = out + BB * DD;

    k_ht<<<dim3(64, 8), 256>>>(src, Win);
    k_attn<<<dim3(NSPLIT, BB), 256>>>(mb, lens, align);
    k_post<<<dim3(64, 8), 512>>>(src, Wout, lens, attn_h, align);
}